// round 3
// baseline (speedup 1.0000x reference)
#include <cuda_runtime.h>
#include <math.h>

#define SS 1024
#define CA 1024
#define CS 512
#define NH 16

// ---------------- scratch (static __device__, no allocs) ----------------
__device__ float d_an[SS*CA];
__device__ float d_sn[SS*CS];
__device__ float d_P1[SS*CA];
__device__ float d_P2[SS*CA];
__device__ float d_a1[SS*CA];
__device__ float d_Q [SS*CA];
__device__ float d_KVG[SS*3*CA];
__device__ float d_B [NH*SS*SS];   // pair bias, flat [i,j,h] == [h,x,y]
__device__ float d_Sc[NH*SS*SS];   // scores [h,x,y]
__device__ float d_M [NH*SS];
__device__ float d_Zi[NH*SS];      // 1/Z
__device__ float d_GO[SS*CA];
__device__ float d_A2[SS*CA];
__device__ float d_SD[SS*CA];

// ---------------- fast exp / sigmoid (FMA-only, no MUFU) ----------------
__device__ __forceinline__ float fexp(float x) {
    float y = x * 1.44269504088896341f;
    y = fminf(fmaxf(y, -120.f), 126.f);
    float t = y + 12582912.f;                      // round-to-nearest-int trick
    int   i = __float_as_int(t) - 0x4B400000;
    float f = y - (t - 12582912.f);                // f in [-0.5, 0.5]
    float p = 1.3333558e-3f;
    p = fmaf(p, f, 9.6181291e-3f);
    p = fmaf(p, f, 5.5504109e-2f);
    p = fmaf(p, f, 2.4022651e-1f);
    p = fmaf(p, f, 6.9314718e-1f);
    p = fmaf(p, f, 1.0f);
    return p * __int_as_float((i + 127) << 23);
}
__device__ __forceinline__ float fsig(float v) { return 1.f / (1.f + fexp(-v)); }

// ---------------- LayerNorm over rows ----------------
__global__ void ln_kernel(const float* __restrict__ x, const float* __restrict__ w,
                          float* __restrict__ y, int C) {
    int row = blockIdx.x;
    const float* xr = x + (long long)row * C;
    float*       yr = y + (long long)row * C;
    float s = 0.f, s2 = 0.f;
    for (int i = threadIdx.x; i < C; i += blockDim.x) { float v = xr[i]; s += v; s2 += v*v; }
    __shared__ float sh[64];
    #pragma unroll
    for (int o = 16; o; o >>= 1) { s += __shfl_xor_sync(~0u, s, o); s2 += __shfl_xor_sync(~0u, s2, o); }
    int wid = threadIdx.x >> 5, lid = threadIdx.x & 31;
    if (lid == 0) { sh[wid] = s; sh[wid + 32] = s2; }
    __syncthreads();
    if (threadIdx.x == 0) {
        float a = 0.f, b = 0.f; int nw = blockDim.x >> 5;
        for (int i = 0; i < nw; i++) { a += sh[i]; b += sh[i + 32]; }
        float mean = a / C;
        float var  = b / C - mean * mean;
        sh[0] = mean; sh[1] = rsqrtf(var + 1e-5f);
    }
    __syncthreads();
    float mean = sh[0], inv = sh[1];
    for (int i = threadIdx.x; i < C; i += blockDim.x) {
        float v = (xr[i] - mean) * inv;
        if (w) v *= w[i];
        yr[i] = v;
    }
}

// ---------------- z LayerNorm + bias projection: 1M rows of 64 -> 16 ----------------
__global__ __launch_bounds__(128) void zbias_kernel(
    const float* __restrict__ z, const float* __restrict__ pnw, const float* __restrict__ pnb,
    const float* __restrict__ bw, const float* __restrict__ bb, float* __restrict__ out) {
    __shared__ float zt[128 * 65];
    __shared__ float w[16][64];
    __shared__ float wn[64], wb[64], bbs[16];
    int t = threadIdx.x;
    for (int i = t; i < 16 * 64; i += 128) w[i >> 6][i & 63] = bw[i];
    for (int i = t; i < 64; i += 128) { wn[i] = pnw[i]; wb[i] = pnb[i]; }
    if (t < 16) bbs[t] = bb[t];
    long long r0 = (long long)blockIdx.x * 128;
    const float* zp = z + r0 * 64;
    #pragma unroll
    for (int it = 0; it < 16; it++) {
        int idx = it * 512 + t * 4;
        float4 v = *(const float4*)(zp + idx);
        int r = idx >> 6, c = idx & 63;
        float* dst = &zt[r * 65 + c];
        dst[0] = v.x; dst[1] = v.y; dst[2] = v.z; dst[3] = v.w;
    }
    __syncthreads();
    float x[64]; float s = 0.f;
    #pragma unroll
    for (int k = 0; k < 64; k++) { x[k] = zt[t * 65 + k]; s += x[k]; }
    float mean = s * (1.f / 64.f), v2 = 0.f;
    #pragma unroll
    for (int k = 0; k < 64; k++) { float d = x[k] - mean; v2 += d * d; }
    float inv = rsqrtf(v2 * (1.f / 64.f) + 1e-5f);
    #pragma unroll
    for (int k = 0; k < 64; k++) x[k] = (x[k] - mean) * inv * wn[k] + wb[k];
    float acc[16];
    #pragma unroll
    for (int h = 0; h < 16; h++) acc[h] = bbs[h];
    #pragma unroll
    for (int k = 0; k < 64; k++) {
        float xv = x[k];
        #pragma unroll
        for (int h = 0; h < 16; h++) acc[h] = fmaf(xv, w[h][k], acc[h]);
    }
    float* op = out + (r0 + t) * 16;
    #pragma unroll
    for (int h = 0; h < 16; h += 4)
        *(float4*)(op + h) = make_float4(acc[h], acc[h+1], acc[h+2], acc[h+3]);
}

// ---------------- generic fp32 GEMM: C = scale*(A·B^T) [+bias[n]] [+Cadd] ----------------
// A[M,K] lda, B[N,K] ldb, batched by blockIdx.z strides. Tiles 64x64, BK=16.
__global__ __launch_bounds__(256) void gemm_nt(
    const float* __restrict__ Ag, int lda, long long sA,
    const float* __restrict__ Bg, int ldb, long long sB,
    float* __restrict__ Cg, int ldc, long long sC,
    const float* __restrict__ bias,
    const float* __restrict__ CaddG, long long sAdd,
    int K, float scale) {
    const float* A = Ag + (long long)blockIdx.z * sA;
    const float* B = Bg + (long long)blockIdx.z * sB;
    float*       C = Cg + (long long)blockIdx.z * sC;
    const float* Cadd = CaddG ? CaddG + (long long)blockIdx.z * sAdd : nullptr;
    __shared__ float As[16][64];
    __shared__ float Bs[16][64];
    int t = threadIdx.x;
    int tx = t & 15, ty = t >> 4;
    int m0 = blockIdx.y * 64, n0 = blockIdx.x * 64;
    int lr = t >> 2;          // 0..63
    int lc = (t & 3) * 4;     // 0,4,8,12
    const float* Ap = A + (long long)(m0 + lr) * lda + lc;
    const float* Bp = B + (long long)(n0 + lr) * ldb + lc;
    float acc[4][4] = {};
    for (int k0 = 0; k0 < K; k0 += 16) {
        float4 av = *(const float4*)(Ap + k0);
        float4 bv = *(const float4*)(Bp + k0);
        __syncthreads();
        As[lc+0][lr] = av.x; As[lc+1][lr] = av.y; As[lc+2][lr] = av.z; As[lc+3][lr] = av.w;
        Bs[lc+0][lr] = bv.x; Bs[lc+1][lr] = bv.y; Bs[lc+2][lr] = bv.z; Bs[lc+3][lr] = bv.w;
        __syncthreads();
        #pragma unroll
        for (int k = 0; k < 16; k++) {
            float4 a4 = *(const float4*)&As[k][ty * 4];
            float4 b4 = *(const float4*)&Bs[k][tx * 4];
            float ra[4] = {a4.x, a4.y, a4.z, a4.w};
            float rb[4] = {b4.x, b4.y, b4.z, b4.w};
            #pragma unroll
            for (int i = 0; i < 4; i++)
                #pragma unroll
                for (int j = 0; j < 4; j++)
                    acc[i][j] = fmaf(ra[i], rb[j], acc[i][j]);
        }
    }
    #pragma unroll
    for (int i = 0; i < 4; i++) {
        int m = m0 + ty * 4 + i;
        int n = n0 + tx * 4;
        float4 o = make_float4(acc[i][0]*scale, acc[i][1]*scale, acc[i][2]*scale, acc[i][3]*scale);
        if (bias) { o.x += bias[n]; o.y += bias[n+1]; o.z += bias[n+2]; o.w += bias[n+3]; }
        if (Cadd) {
            float4 c4 = *(const float4*)(Cadd + (long long)m * ldc + n);
            o.x += c4.x; o.y += c4.y; o.z += c4.z; o.w += c4.w;
        }
        *(float4*)(C + (long long)m * ldc + n) = o;
    }
}

// ---------------- elementwise (float4 vectorized) ----------------
__global__ void a1_kernel(const float4* __restrict__ P1, const float4* __restrict__ P2,
                          const float4* __restrict__ an, float4* __restrict__ o) {
    int i = blockIdx.x * 256 + threadIdx.x;
    float4 p1 = P1[i], p2 = P2[i], av = an[i], r;
    r.x = fsig(fmaf(p1.x, av.x, p2.x));
    r.y = fsig(fmaf(p1.y, av.y, p2.y));
    r.z = fsig(fmaf(p1.z, av.z, p2.z));
    r.w = fsig(fmaf(p1.w, av.w, p2.w));
    o[i] = r;
}
__global__ void final_kernel(const float4* __restrict__ SD, const float4* __restrict__ A2,
                             float4* __restrict__ o) {
    int i = blockIdx.x * 256 + threadIdx.x;
    float4 sd = SD[i], a2 = A2[i], r;
    r.x = fsig(sd.x) * a2.x;
    r.y = fsig(sd.y) * a2.y;
    r.z = fsig(sd.z) * a2.z;
    r.w = fsig(sd.w) * a2.w;
    o[i] = r;
}

// ---------------- row softmax stats: max & 1/sumexp per (h,x) row ----------------
__global__ __launch_bounds__(256) void stats_kernel(const float* __restrict__ Sc,
                                                    float* __restrict__ Mo, float* __restrict__ Zi) {
    long long row = blockIdx.x;
    const float* p = Sc + row * 1024;
    int t = threadIdx.x;
    float4 v = *(const float4*)(p + t * 4);
    float mx = fmaxf(fmaxf(v.x, v.y), fmaxf(v.z, v.w));
    __shared__ float sh[8];
    #pragma unroll
    for (int o = 16; o; o >>= 1) mx = fmaxf(mx, __shfl_xor_sync(~0u, mx, o));
    if ((t & 31) == 0) sh[t >> 5] = mx;
    __syncthreads();
    if (t == 0) { float m = sh[0]; for (int i = 1; i < 8; i++) m = fmaxf(m, sh[i]); sh[0] = m; }
    __syncthreads();
    mx = sh[0];
    float sum = fexp(v.x - mx) + fexp(v.y - mx) + fexp(v.z - mx) + fexp(v.w - mx);
    #pragma unroll
    for (int o = 16; o; o >>= 1) sum += __shfl_xor_sync(~0u, sum, o);
    __syncthreads();
    if ((t & 31) == 0) sh[t >> 5] = sum;
    __syncthreads();
    if (t == 0) { float s = 0.f; for (int i = 0; i < 8; i++) s += sh[i]; Mo[row] = mx; Zi[row] = 1.f / s; }
}

// ---------------- AV: GO[h,j,c] = sigmoid(g)*sum_x exp(Sc[h,x,j]-M)*Zi*V[h,x,c] ----------------
__global__ __launch_bounds__(256) void av_kernel(
    const float* __restrict__ Sc, const float* __restrict__ Mx, const float* __restrict__ Zi,
    const float* __restrict__ KVG, float* __restrict__ GO) {
    int h = blockIdx.z;
    int j0 = blockIdx.x * 64;
    const float* Sch = Sc + (long long)h * (1 << 20);
    const float* Mh  = Mx + (h << 10);
    const float* Zh  = Zi + (h << 10);
    const float* Vh  = KVG + (long long)h * 196608 + 64;
    const float* Gh  = KVG + (long long)h * 196608 + 128;
    float*       GOh = GO + (long long)h * 65536;
    __shared__ float Es[32][68];
    __shared__ float Vs[32][68];
    int t = threadIdx.x, tx = t & 15, ty = t >> 4;
    float acc[4][4] = {};
    for (int x0 = 0; x0 < 1024; x0 += 32) {
        __syncthreads();
        #pragma unroll
        for (int q = 0; q < 2; q++) {
            int slot = t + q * 256;         // 0..511
            int r = slot >> 4;              // 0..31
            int c4 = (slot & 15) * 4;       // 0..60
            float m  = Mh[x0 + r];
            float rz = Zh[x0 + r];
            float4 e = *(const float4*)(Sch + (long long)(x0 + r) * 1024 + j0 + c4);
            e.x = fexp(e.x - m); e.y = fexp(e.y - m); e.z = fexp(e.z - m); e.w = fexp(e.w - m);
            *(float4*)&Es[r][c4] = e;
            float4 vv = *(const float4*)(Vh + (long long)(x0 + r) * 192 + c4);
            vv.x *= rz; vv.y *= rz; vv.z *= rz; vv.w *= rz;
            *(float4*)&Vs[r][c4] = vv;
        }
        __syncthreads();
        #pragma unroll
        for (int x = 0; x < 32; x++) {
            float4 e = *(const float4*)&Es[x][ty * 4];
            float4 v = *(const float4*)&Vs[x][tx * 4];
            float re[4] = {e.x, e.y, e.z, e.w};
            float rv[4] = {v.x, v.y, v.z, v.w};
            #pragma unroll
            for (int i = 0; i < 4; i++)
                #pragma unroll
                for (int j = 0; j < 4; j++)
                    acc[i][j] = fmaf(re[i], rv[j], acc[i][j]);
        }
    }
    #pragma unroll
    for (int i = 0; i < 4; i++) {
        int j = j0 + ty * 4 + i;
        float4 g4 = *(const float4*)(Gh + (long long)j * 192 + tx * 4);
        float4 o;
        o.x = acc[i][0] * fsig(g4.x);
        o.y = acc[i][1] * fsig(g4.y);
        o.z = acc[i][2] * fsig(g4.z);
        o.w = acc[i][3] * fsig(g4.w);
        *(float4*)(GOh + (long long)j * 64 + tx * 4) = o;
    }
}

// ---------------- driver ----------------
extern "C" void kernel_launch(void* const* d_in, const int* in_sizes, int n_in,
                              void* d_out, int out_size) {
    const float* a      = (const float*)d_in[0];
    const float* z      = (const float*)d_in[1];
    const float* s      = (const float*)d_in[2];
    const float* sn_w   = (const float*)d_in[3];
    const float* pb_w   = (const float*)d_in[4];
    const float* pb_b   = (const float*)d_in[5];
    const float* pn_w   = (const float*)d_in[6];
    const float* pnorm_w= (const float*)d_in[7];
    const float* pnorm_b= (const float*)d_in[8];
    const float* q_w    = (const float*)d_in[9];
    const float* q_b    = (const float*)d_in[10];
    const float* kvg_w  = (const float*)d_in[11];
    const float* bias_w = (const float*)d_in[12];
    const float* bias_b = (const float*)d_in[13];
    const float* attn_w = (const float*)d_in[14];
    const float* out_w  = (const float*)d_in[15];
    const float* out_b  = (const float*)d_in[16];
    float* out = (float*)d_out;

    float *an, *sn, *P1, *P2, *a1, *Q, *KVG, *Bm, *Sc, *Mx, *Zi, *GO, *A2, *SD;
    cudaGetSymbolAddress((void**)&an, d_an);
    cudaGetSymbolAddress((void**)&sn, d_sn);
    cudaGetSymbolAddress((void**)&P1, d_P1);
    cudaGetSymbolAddress((void**)&P2, d_P2);
    cudaGetSymbolAddress((void**)&a1, d_a1);
    cudaGetSymbolAddress((void**)&Q,  d_Q);
    cudaGetSymbolAddress((void**)&KVG,d_KVG);
    cudaGetSymbolAddress((void**)&Bm, d_B);
    cudaGetSymbolAddress((void**)&Sc, d_Sc);
    cudaGetSymbolAddress((void**)&Mx, d_M);
    cudaGetSymbolAddress((void**)&Zi, d_Zi);
    cudaGetSymbolAddress((void**)&GO, d_GO);
    cudaGetSymbolAddress((void**)&A2, d_A2);
    cudaGetSymbolAddress((void**)&SD, d_SD);

    // 1) LayerNorms
    ln_kernel<<<SS, 256>>>(a, nullptr, an, CA);
    ln_kernel<<<SS, 256>>>(s, sn_w,  sn, CS);

    // 2) P1 = sn@pb_w^T + pb_b ; P2 = sn@pn_w^T
    gemm_nt<<<dim3(16,16,1), 256>>>(sn, CS, 0, pb_w, CS, 0, P1, CA, 0, pb_b, nullptr, 0, CS, 1.f);
    gemm_nt<<<dim3(16,16,1), 256>>>(sn, CS, 0, pn_w, CS, 0, P2, CA, 0, nullptr, nullptr, 0, CS, 1.f);

    // 3) a1 = sigmoid(P1*an + P2)
    a1_kernel<<<1024, 256>>>((const float4*)P1, (const float4*)P2, (const float4*)an, (float4*)a1);

    // 4) Q and KVG projections
    gemm_nt<<<dim3(16,16,1), 256>>>(a1, CA, 0, q_w,   CA, 0, Q,   CA,   0, q_b,    nullptr, 0, CA, 1.f);
    gemm_nt<<<dim3(48,16,1), 256>>>(a1, CA, 0, kvg_w, CA, 0, KVG, 3*CA, 0, nullptr, nullptr, 0, CA, 1.f);

    // 5) pair bias from z (LN + projection), flat layout == [h,x,y]
    zbias_kernel<<<8192, 128>>>(z, pnorm_w, pnorm_b, bias_w, bias_b, Bm);

    // 6) scores Sc[h,x,y] = K[x]·Q[y]/64 + bias  (batched over heads)
    gemm_nt<<<dim3(16,16,NH), 256>>>(KVG, 192, 196608, Q, 64, 65536,
                                     Sc, 1024, 1 << 20, nullptr, Bm, 1 << 20, 64, 1.f/64.f);

    // 7) softmax row stats
    stats_kernel<<<NH*SS, 256>>>(Sc, Mx, Zi);

    // 8) O = P^T V, gated by sigmoid(g); GO flat == [S,ca]
    av_kernel<<<dim3(16,1,NH), 256>>>(Sc, Mx, Zi, KVG, GO);

    // 9) a2 = GO@attn_w^T ; SD = s@out_w^T + out_b
    gemm_nt<<<dim3(16,16,1), 256>>>(GO, CA, 0, attn_w, CA, 0, A2, CA, 0, nullptr, nullptr, 0, CA, 1.f);
    gemm_nt<<<dim3(16,16,1), 256>>>(s,  CS, 0, out_w,  CS, 0, SD, CA, 0, out_b,  nullptr, 0, CS, 1.f);

    // 10) out = sigmoid(SD) * a2
    final_kernel<<<1024, 256>>>((const float4*)SD, (const float4*)A2, (float4*)out);
}

// round 5
// speedup vs baseline: 1.2638x; 1.2638x over previous
#include <cuda_runtime.h>
#include <math.h>

#define SS 1024
#define CA 1024
#define CS 512
#define NH 16

// ---------------- scratch (static __device__, no allocs) ----------------
__device__ float d_an[SS*CA];
__device__ float d_sn[SS*CS];
__device__ float d_P1[SS*CA];
__device__ float d_P2[SS*CA];
__device__ float d_a1[SS*CA];
__device__ float d_Q [SS*CA];
__device__ float d_KVG[SS*3*CA];
__device__ float d_B [NH*SS*SS];   // pair bias, flat [i,j,h] == [h,x,y]
__device__ float d_Sc[NH*SS*SS];   // scores [h,x,y]
__device__ float d_M [NH*SS];
__device__ float d_Zi[NH*SS];      // 1/Z
__device__ float d_GO[SS*CA];
__device__ float d_A2[SS*CA];
__device__ float d_SD[SS*CA];

// ---------------- fast exp / sigmoid (FMA-only, no MUFU) ----------------
__device__ __forceinline__ float fexp(float x) {
    float y = x * 1.44269504088896341f;
    y = fminf(fmaxf(y, -120.f), 126.f);
    float t = y + 12582912.f;
    int   i = __float_as_int(t) - 0x4B400000;
    float f = y - (t - 12582912.f);
    float p = 1.3333558e-3f;
    p = fmaf(p, f, 9.6181291e-3f);
    p = fmaf(p, f, 5.5504109e-2f);
    p = fmaf(p, f, 2.4022651e-1f);
    p = fmaf(p, f, 6.9314718e-1f);
    p = fmaf(p, f, 1.0f);
    return p * __int_as_float((i + 127) << 23);
}
__device__ __forceinline__ float fsig(float v) { return 1.f / (1.f + fexp(-v)); }

// ---------------- tf32 mma helpers ----------------
__device__ __forceinline__ unsigned cvt_tf32(float x) {
    unsigned r; asm("cvt.rna.tf32.f32 %0, %1;" : "=r"(r) : "f"(x)); return r;
}
__device__ __forceinline__ void split_tf32(float x, unsigned& hi, unsigned& lo) {
    hi = cvt_tf32(x);
    lo = cvt_tf32(x - __uint_as_float(hi));
}
__device__ __forceinline__ void mma8(float* d, const unsigned* a, const unsigned* b) {
    asm volatile(
        "mma.sync.aligned.m16n8k8.row.col.f32.tf32.tf32.f32 "
        "{%0,%1,%2,%3}, {%4,%5,%6,%7}, {%8,%9}, {%0,%1,%2,%3};"
        : "+f"(d[0]), "+f"(d[1]), "+f"(d[2]), "+f"(d[3])
        : "r"(a[0]), "r"(a[1]), "r"(a[2]), "r"(a[3]), "r"(b[0]), "r"(b[1]));
}

// ---------------- LayerNorm over rows ----------------
__global__ void ln_kernel(const float* __restrict__ x, const float* __restrict__ w,
                          float* __restrict__ y, int C) {
    int row = blockIdx.x;
    const float* xr = x + (long long)row * C;
    float*       yr = y + (long long)row * C;
    float s = 0.f, s2 = 0.f;
    for (int i = threadIdx.x; i < C; i += blockDim.x) { float v = xr[i]; s += v; s2 += v*v; }
    __shared__ float sh[64];
    #pragma unroll
    for (int o = 16; o; o >>= 1) { s += __shfl_xor_sync(~0u, s, o); s2 += __shfl_xor_sync(~0u, s2, o); }
    int wid = threadIdx.x >> 5, lid = threadIdx.x & 31;
    if (lid == 0) { sh[wid] = s; sh[wid + 32] = s2; }
    __syncthreads();
    if (threadIdx.x == 0) {
        float a = 0.f, b = 0.f; int nw = blockDim.x >> 5;
        for (int i = 0; i < nw; i++) { a += sh[i]; b += sh[i + 32]; }
        float mean = a / C;
        float var  = b / C - mean * mean;
        sh[0] = mean; sh[1] = rsqrtf(var + 1e-5f);
    }
    __syncthreads();
    float mean = sh[0], inv = sh[1];
    for (int i = threadIdx.x; i < C; i += blockDim.x) {
        float v = (xr[i] - mean) * inv;
        if (w) v *= w[i];
        yr[i] = v;
    }
}

// ---------------- z LayerNorm + bias projection: 1M rows of 64 -> 16 ----------------
__global__ __launch_bounds__(128) void zbias_kernel(
    const float* __restrict__ z, const float* __restrict__ pnw, const float* __restrict__ pnb,
    const float* __restrict__ bw, const float* __restrict__ bb, float* __restrict__ out) {
    __shared__ float zt[128 * 65];
    __shared__ float w[16][64];
    __shared__ float wn[64], wb[64], bbs[16];
    int t = threadIdx.x;
    for (int i = t; i < 16 * 64; i += 128) w[i >> 6][i & 63] = bw[i];
    for (int i = t; i < 64; i += 128) { wn[i] = pnw[i]; wb[i] = pnb[i]; }
    if (t < 16) bbs[t] = bb[t];
    long long r0 = (long long)blockIdx.x * 128;
    const float* zp = z + r0 * 64;
    #pragma unroll
    for (int it = 0; it < 16; it++) {
        int idx = it * 512 + t * 4;
        float4 v = *(const float4*)(zp + idx);
        int r = idx >> 6, c = idx & 63;
        float* dst = &zt[r * 65 + c];
        dst[0] = v.x; dst[1] = v.y; dst[2] = v.z; dst[3] = v.w;
    }
    __syncthreads();
    float x[64]; float s = 0.f;
    #pragma unroll
    for (int k = 0; k < 64; k++) { x[k] = zt[t * 65 + k]; s += x[k]; }
    float mean = s * (1.f / 64.f), v2 = 0.f;
    #pragma unroll
    for (int k = 0; k < 64; k++) { float d = x[k] - mean; v2 += d * d; }
    float inv = rsqrtf(v2 * (1.f / 64.f) + 1e-5f);
    #pragma unroll
    for (int k = 0; k < 64; k++) x[k] = (x[k] - mean) * inv * wn[k] + wb[k];
    float acc[16];
    #pragma unroll
    for (int h = 0; h < 16; h++) acc[h] = bbs[h];
    #pragma unroll
    for (int k = 0; k < 64; k++) {
        float xv = x[k];
        #pragma unroll
        for (int h = 0; h < 16; h++) acc[h] = fmaf(xv, w[h][k], acc[h]);
    }
    float* op = out + (r0 + t) * 16;
    #pragma unroll
    for (int h = 0; h < 16; h += 4)
        *(float4*)(op + h) = make_float4(acc[h], acc[h+1], acc[h+2], acc[h+3]);
}

// ---------------- 3xTF32 tensor-core GEMM: C = scale*(A·B^T) [+bias[n]] [+Cadd] ----------------
// A[M,K] lda, B[N,K] ldb, batched via blockIdx.z strides. 64x64 block tile, BK=16,
// 128 threads = 4 warps in 2x2; each warp 32x32 via 2 m16 x 4 n8 mma tiles.
__global__ __launch_bounds__(128) void gemm_tf32(
    const float* __restrict__ Ag, int lda, long long sA,
    const float* __restrict__ Bg, int ldb, long long sB,
    float* __restrict__ Cg, int ldc, long long sC,
    const float* __restrict__ bias,
    const float* __restrict__ CaddG, long long sAdd,
    int K, float scale) {
    const float* A = Ag + (long long)blockIdx.z * sA;
    const float* B = Bg + (long long)blockIdx.z * sB;
    float*       C = Cg + (long long)blockIdx.z * sC;
    const float* Cadd = CaddG ? CaddG + (long long)blockIdx.z * sAdd : nullptr;
    __shared__ float As[64][17];
    __shared__ float Bs[64][17];
    int t = threadIdx.x;
    int lane = t & 31, wid = t >> 5;
    int wm = (wid >> 1) * 32, wn = (wid & 1) * 32;
    int g = lane >> 2, c = lane & 3;
    int m0 = blockIdx.y * 64, n0 = blockIdx.x * 64;
    int lrow = t >> 2;            // 0..31
    int lc4  = (t & 3) * 4;       // 0,4,8,12
    float d[2][4][4] = {};
    for (int k0 = 0; k0 < K; k0 += 16) {
        float4 av0 = *(const float4*)(A + (long long)(m0 + lrow)      * lda + k0 + lc4);
        float4 av1 = *(const float4*)(A + (long long)(m0 + lrow + 32) * lda + k0 + lc4);
        float4 bv0 = *(const float4*)(B + (long long)(n0 + lrow)      * ldb + k0 + lc4);
        float4 bv1 = *(const float4*)(B + (long long)(n0 + lrow + 32) * ldb + k0 + lc4);
        __syncthreads();
        As[lrow][lc4+0]=av0.x; As[lrow][lc4+1]=av0.y; As[lrow][lc4+2]=av0.z; As[lrow][lc4+3]=av0.w;
        As[lrow+32][lc4+0]=av1.x; As[lrow+32][lc4+1]=av1.y; As[lrow+32][lc4+2]=av1.z; As[lrow+32][lc4+3]=av1.w;
        Bs[lrow][lc4+0]=bv0.x; Bs[lrow][lc4+1]=bv0.y; Bs[lrow][lc4+2]=bv0.z; Bs[lrow][lc4+3]=bv0.w;
        Bs[lrow+32][lc4+0]=bv1.x; Bs[lrow+32][lc4+1]=bv1.y; Bs[lrow+32][lc4+2]=bv1.z; Bs[lrow+32][lc4+3]=bv1.w;
        __syncthreads();
        #pragma unroll
        for (int ks = 0; ks < 16; ks += 8) {
            unsigned ah[2][4], al[2][4], bh[4][2], bl[4][2];
            #pragma unroll
            for (int mt = 0; mt < 2; mt++) {
                int r = wm + mt * 16 + g;
                split_tf32(As[r    ][ks + c    ], ah[mt][0], al[mt][0]);
                split_tf32(As[r + 8][ks + c    ], ah[mt][1], al[mt][1]);
                split_tf32(As[r    ][ks + c + 4], ah[mt][2], al[mt][2]);
                split_tf32(As[r + 8][ks + c + 4], ah[mt][3], al[mt][3]);
            }
            #pragma unroll
            for (int nt = 0; nt < 4; nt++) {
                int nn = wn + nt * 8 + g;
                split_tf32(Bs[nn][ks + c    ], bh[nt][0], bl[nt][0]);
                split_tf32(Bs[nn][ks + c + 4], bh[nt][1], bl[nt][1]);
            }
            #pragma unroll
            for (int mt = 0; mt < 2; mt++)
                #pragma unroll
                for (int nt = 0; nt < 4; nt++) {
                    mma8(d[mt][nt], ah[mt], bh[nt]);
                    mma8(d[mt][nt], ah[mt], bl[nt]);
                    mma8(d[mt][nt], al[mt], bh[nt]);
                }
        }
    }
    // epilogue: c0,c1 -> (row g, col 2c..2c+1); c2,c3 -> row g+8
    #pragma unroll
    for (int mt = 0; mt < 2; mt++) {
        #pragma unroll
        for (int nt = 0; nt < 4; nt++) {
            int row0 = m0 + wm + mt * 16 + g;
            int col  = n0 + wn + nt * 8 + 2 * c;
            #pragma unroll
            for (int half = 0; half < 2; half++) {
                int m = row0 + half * 8;
                float v0 = d[mt][nt][half * 2 + 0] * scale;
                float v1 = d[mt][nt][half * 2 + 1] * scale;
                if (bias) { v0 += bias[col]; v1 += bias[col + 1]; }
                if (Cadd) {
                    v0 += Cadd[(long long)m * ldc + col];
                    v1 += Cadd[(long long)m * ldc + col + 1];
                }
                *(float2*)(C + (long long)m * ldc + col) = make_float2(v0, v1);
            }
        }
    }
}

// ---------------- elementwise (float4 vectorized) ----------------
__global__ void a1_kernel(const float4* __restrict__ P1, const float4* __restrict__ P2,
                          const float4* __restrict__ an, float4* __restrict__ o) {
    int i = blockIdx.x * 256 + threadIdx.x;
    float4 p1 = P1[i], p2 = P2[i], av = an[i], r;
    r.x = fsig(fmaf(p1.x, av.x, p2.x));
    r.y = fsig(fmaf(p1.y, av.y, p2.y));
    r.z = fsig(fmaf(p1.z, av.z, p2.z));
    r.w = fsig(fmaf(p1.w, av.w, p2.w));
    o[i] = r;
}
__global__ void final_kernel(const float4* __restrict__ SD, const float4* __restrict__ A2,
                             float4* __restrict__ o) {
    int i = blockIdx.x * 256 + threadIdx.x;
    float4 sd = SD[i], a2 = A2[i], r;
    r.x = fsig(sd.x) * a2.x;
    r.y = fsig(sd.y) * a2.y;
    r.z = fsig(sd.z) * a2.z;
    r.w = fsig(sd.w) * a2.w;
    o[i] = r;
}

// ---------------- row softmax stats ----------------
__global__ __launch_bounds__(256) void stats_kernel(const float* __restrict__ Sc,
                                                    float* __restrict__ Mo, float* __restrict__ Zi) {
    long long row = blockIdx.x;
    const float* p = Sc + row * 1024;
    int t = threadIdx.x;
    float4 v = *(const float4*)(p + t * 4);
    float mx = fmaxf(fmaxf(v.x, v.y), fmaxf(v.z, v.w));
    __shared__ float sh[8];
    #pragma unroll
    for (int o = 16; o; o >>= 1) mx = fmaxf(mx, __shfl_xor_sync(~0u, mx, o));
    if ((t & 31) == 0) sh[t >> 5] = mx;
    __syncthreads();
    if (t == 0) { float m = sh[0]; for (int i = 1; i < 8; i++) m = fmaxf(m, sh[i]); sh[0] = m; }
    __syncthreads();
    mx = sh[0];
    float sum = fexp(v.x - mx) + fexp(v.y - mx) + fexp(v.z - mx) + fexp(v.w - mx);
    #pragma unroll
    for (int o = 16; o; o >>= 1) sum += __shfl_xor_sync(~0u, sum, o);
    __syncthreads();
    if ((t & 31) == 0) sh[t >> 5] = sum;
    __syncthreads();
    if (t == 0) { float s = 0.f; for (int i = 0; i < 8; i++) s += sh[i]; Mo[row] = mx; Zi[row] = 1.f / s; }
}

// ---------------- AV via 3xTF32 mma: GO[j,c] = sig(g)*sum_x E[x,j]*Zi[x]*V[x,c] ----------------
// grid (16 j-blocks, 16 heads), 128 threads. A[m=j][k=x] = Es[x][j], B[n=c][k=x] = Vs[x][c].
__global__ __launch_bounds__(128) void av_tf32(
    const float* __restrict__ Sc, const float* __restrict__ Mx, const float* __restrict__ Zi,
    const float* __restrict__ KVG, float* __restrict__ GO) {
    int h = blockIdx.y;
    int j0 = blockIdx.x * 64;
    const float* Sch = Sc + (long long)h * (1 << 20);
    const float* Mh  = Mx + (h << 10);
    const float* Zh  = Zi + (h << 10);
    const float* Vh  = KVG + (long long)h * 196608 + 64;
    const float* Gh  = KVG + (long long)h * 196608 + 128;
    float*       GOh = GO + (long long)h * 65536;
    __shared__ float Es[16][68];
    __shared__ float Vs[16][68];
    int t = threadIdx.x;
    int lane = t & 31, wid = t >> 5;
    int wm = (wid >> 1) * 32, wn = (wid & 1) * 32;
    int g = lane >> 2, c = lane & 3;
    float d[2][4][4] = {};
    for (int x0 = 0; x0 < 1024; x0 += 16) {
        __syncthreads();
        #pragma unroll
        for (int i = 0; i < 2; i++) {
            int idx = t + i * 128;
            int x  = idx >> 4;
            int c4 = (idx & 15) * 4;
            float m  = Mh[x0 + x];
            float rz = Zh[x0 + x];
            float4 e = *(const float4*)(Sch + (long long)(x0 + x) * 1024 + j0 + c4);
            e.x = fexp(e.x - m); e.y = fexp(e.y - m); e.z = fexp(e.z - m); e.w = fexp(e.w - m);
            *(float4*)&Es[x][c4] = e;
            float4 vv = *(const float4*)(Vh + (long long)(x0 + x) * 192 + c4);
            vv.x *= rz; vv.y *= rz; vv.z *= rz; vv.w *= rz;
            *(float4*)&Vs[x][c4] = vv;
        }
        __syncthreads();
        #pragma unroll
        for (int ks = 0; ks < 16; ks += 8) {
            unsigned ah[2][4], al[2][4], bh[4][2], bl[4][2];
            #pragma unroll
            for (int mt = 0; mt < 2; mt++) {
                int r = wm + mt * 16 + g;
                split_tf32(Es[ks + c    ][r    ], ah[mt][0], al[mt][0]);
                split_tf32(Es[ks + c    ][r + 8], ah[mt][1], al[mt][1]);
                split_tf32(Es[ks + c + 4][r    ], ah[mt][2], al[mt][2]);
                split_tf32(Es[ks + c + 4][r + 8], ah[mt][3], al[mt][3]);
            }
            #pragma unroll
            for (int nt = 0; nt < 4; nt++) {
                int nn = wn + nt * 8 + g;
                split_tf32(Vs[ks + c    ][nn], bh[nt][0], bl[nt][0]);
                split_tf32(Vs[ks + c + 4][nn], bh[nt][1], bl[nt][1]);
            }
            #pragma unroll
            for (int mt = 0; mt < 2; mt++)
                #pragma unroll
                for (int nt = 0; nt < 4; nt++) {
                    mma8(d[mt][nt], ah[mt], bh[nt]);
                    mma8(d[mt][nt], ah[mt], bl[nt]);
                    mma8(d[mt][nt], al[mt], bh[nt]);
                }
        }
    }
    #pragma unroll
    for (int mt = 0; mt < 2; mt++) {
        #pragma unroll
        for (int nt = 0; nt < 4; nt++) {
            int j0r = j0 + wm + mt * 16 + g;
            int cc  = wn + nt * 8 + 2 * c;
            #pragma unroll
            for (int half = 0; half < 2; half++) {
                int j = j0r + half * 8;
                float g0 = fsig(Gh[(long long)j * 192 + cc]);
                float g1 = fsig(Gh[(long long)j * 192 + cc + 1]);
                float v0 = d[mt][nt][half * 2 + 0] * g0;
                float v1 = d[mt][nt][half * 2 + 1] * g1;
                *(float2*)(GOh + (long long)j * 64 + cc) = make_float2(v0, v1);
            }
        }
    }
}

// ---------------- driver ----------------
extern "C" void kernel_launch(void* const* d_in, const int* in_sizes, int n_in,
                              void* d_out, int out_size) {
    const float* a      = (const float*)d_in[0];
    const float* z      = (const float*)d_in[1];
    const float* s      = (const float*)d_in[2];
    const float* sn_w   = (const float*)d_in[3];
    const float* pb_w   = (const float*)d_in[4];
    const float* pb_b   = (const float*)d_in[5];
    const float* pn_w   = (const float*)d_in[6];
    const float* pnorm_w= (const float*)d_in[7];
    const float* pnorm_b= (const float*)d_in[8];
    const float* q_w    = (const float*)d_in[9];
    const float* q_b    = (const float*)d_in[10];
    const float* kvg_w  = (const float*)d_in[11];
    const float* bias_w = (const float*)d_in[12];
    const float* bias_b = (const float*)d_in[13];
    const float* attn_w = (const float*)d_in[14];
    const float* out_w  = (const float*)d_in[15];
    const float* out_b  = (const float*)d_in[16];
    float* out = (float*)d_out;

    float *an, *sn, *P1, *P2, *a1, *Q, *KVG, *Bm, *Sc, *Mx, *Zi, *GO, *A2, *SD;
    cudaGetSymbolAddress((void**)&an, d_an);
    cudaGetSymbolAddress((void**)&sn, d_sn);
    cudaGetSymbolAddress((void**)&P1, d_P1);
    cudaGetSymbolAddress((void**)&P2, d_P2);
    cudaGetSymbolAddress((void**)&a1, d_a1);
    cudaGetSymbolAddress((void**)&Q,  d_Q);
    cudaGetSymbolAddress((void**)&KVG,d_KVG);
    cudaGetSymbolAddress((void**)&Bm, d_B);
    cudaGetSymbolAddress((void**)&Sc, d_Sc);
    cudaGetSymbolAddress((void**)&Mx, d_M);
    cudaGetSymbolAddress((void**)&Zi, d_Zi);
    cudaGetSymbolAddress((void**)&GO, d_GO);
    cudaGetSymbolAddress((void**)&A2, d_A2);
    cudaGetSymbolAddress((void**)&SD, d_SD);

    // 1) LayerNorms
    ln_kernel<<<SS, 256>>>(a, nullptr, an, CA);
    ln_kernel<<<SS, 256>>>(s, sn_w,  sn, CS);

    // 2) P1 = sn@pb_w^T + pb_b ; P2 = sn@pn_w^T
    gemm_tf32<<<dim3(16,16,1), 128>>>(sn, CS, 0, pb_w, CS, 0, P1, CA, 0, pb_b, nullptr, 0, CS, 1.f);
    gemm_tf32<<<dim3(16,16,1), 128>>>(sn, CS, 0, pn_w, CS, 0, P2, CA, 0, nullptr, nullptr, 0, CS, 1.f);

    // 3) a1 = sigmoid(P1*an + P2)
    a1_kernel<<<1024, 256>>>((const float4*)P1, (const float4*)P2, (const float4*)an, (float4*)a1);

    // 4) Q and KVG projections
    gemm_tf32<<<dim3(16,16,1), 128>>>(a1, CA, 0, q_w,   CA, 0, Q,   CA,   0, q_b,    nullptr, 0, CA, 1.f);
    gemm_tf32<<<dim3(48,16,1), 128>>>(a1, CA, 0, kvg_w, CA, 0, KVG, 3*CA, 0, nullptr, nullptr, 0, CA, 1.f);

    // 5) pair bias from z (LN + projection), flat layout == [h,x,y]
    zbias_kernel<<<8192, 128>>>(z, pnorm_w, pnorm_b, bias_w, bias_b, Bm);

    // 6) scores Sc[h,x,y] = K[x]·Q[y]/64 + bias
    gemm_tf32<<<dim3(16,16,NH), 128>>>(KVG, 192, 196608, Q, 64, 65536,
                                       Sc, 1024, 1 << 20, nullptr, Bm, 1 << 20, 64, 1.f/64.f);

    // 7) softmax row stats
    stats_kernel<<<NH*SS, 256>>>(Sc, Mx, Zi);

    // 8) O = P^T V, gated by sigmoid(g); GO flat == [S,ca]
    av_tf32<<<dim3(16,16), 128>>>(Sc, Mx, Zi, KVG, GO);

    // 9) a2 = GO@attn_w^T ; SD = s@out_w^T + out_b
    gemm_tf32<<<dim3(16,16,1), 128>>>(GO, CA, 0, attn_w, CA, 0, A2, CA, 0, nullptr, nullptr, 0, CA, 1.f);
    gemm_tf32<<<dim3(16,16,1), 128>>>(s,  CS, 0, out_w,  CS, 0, SD, CA, 0, out_b,  nullptr, 0, CS, 1.f);

    // 10) out = sigmoid(SD) * a2
    final_kernel<<<1024, 256>>>((const float4*)SD, (const float4*)A2, (float4*)out);
}